// round 8
// baseline (speedup 1.0000x reference)
#include <cuda_runtime.h>
#include <math.h>

#define NPTS  14
#define NEDGE 13
#define NF1   3
#define BMAX  65536
#define FDIM  512
#define H1    64
#define H2    32
#define NSEG  (H1 + 1)
#define SROW4 9            // 9 float4 = 36 floats padded row
#define BIGF  1e30f
typedef unsigned long long u64;

// ---------------- scratch ----------------
__device__ float  g_deaths0[NEDGE * BMAX];
__device__ float  g_dmax[BMAX];
__device__ float  g_p0[BMAX];
__device__ float  g_p1b[BMAX];
__device__ float  g_p1d[BMAX];
__device__ float  g_S[2];
__device__ float  g_h2sum[2 * H2];
__device__ float  g_bp[H1];
__device__ float4 g_A4[NSEG * SROW4];
__device__ float4 g_C4[NSEG * SROW4];

__device__ __forceinline__ float warp_red(float v) {
#pragma unroll
    for (int o = 16; o; o >>= 1) v += __shfl_xor_sync(0xffffffffu, v, o);
    return v;
}
__device__ __forceinline__ u64 pack2(float lo, float hi) {
    u64 r;
    asm("mov.b64 %0, {%1, %2};" : "=l"(r) : "f"(lo), "f"(hi));
    return r;
}
__device__ __forceinline__ void unpack2(u64 v, float& lo, float& hi) {
    asm("mov.b64 {%0, %1}, %2;" : "=f"(lo), "=f"(hi) : "l"(v));
}
#define FMA2(ACC, A, B) asm("fma.rn.f32x2 %0, %1, %2, %0;" : "+l"(ACC) : "l"(A), "l"(B))

// ---------------- setup: zeros + breakpoints + segment tables ----------------
__global__ void k_setup(const float* __restrict__ W1, const float* __restrict__ b1,
                        const float* __restrict__ W2, const float* __restrict__ b2,
                        float* ent_slot) {
    __shared__ float sbp[H1];
    __shared__ float st[H1];
    int tid = threadIdx.x;
    if (tid < 2)  g_S[tid] = 0.f;
    if (tid < 64) g_h2sum[tid] = 0.f;
    if (tid == 0) *ent_slot = 0.f;
    if (tid < H1) {
        float w = W1[H1 + tid];
        st[tid] = (w != 0.f) ? (-b1[tid] / w) : __int_as_float(0x7f800000);
    }
    __syncthreads();
    if (tid < H1) {
        float t = st[tid];
        int r = 0;
#pragma unroll
        for (int i = 0; i < H1; i++) {
            float ti = st[i];
            r += (ti < t || (ti == t && i < tid)) ? 1 : 0;
        }
        sbp[r] = t;
        g_bp[r] = t;
    }
    __syncthreads();
    const float INF = __int_as_float(0x7f800000);
    for (int e = tid; e < NSEG * H2; e += blockDim.x) {
        int s = e >> 5, k = e & 31;
        float lo = (s == 0)  ? -INF : sbp[s - 1];
        float hi = (s == H1) ?  INF : sbp[s];
        float rep;
        bool li = isinf(lo), hiinf = isinf(hi);
        if (li && hiinf)      rep = 0.f;
        else if (li)          rep = hi - 1.f;
        else if (hiinf)       rep = lo + 1.f;
        else                  rep = 0.5f * (lo + hi);
        float A = 0.f, C = b2[k];
        for (int j = 0; j < H1; j++) {
            float w = W1[H1 + j], bb = b1[j];
            bool act = (w == 0.f) ? (bb > 0.f) : ((w * rep + bb) > 0.f);
            if (act) {
                float m = W2[j * H2 + k];
                A += w * m;
                C += bb * m;
            }
        }
        ((float*)g_A4)[s * (SROW4 * 4) + k] = A;
        ((float*)g_C4)[s * (SROW4 * 4) + k] = C;
    }
}

// ---------------- MST (Prim, squared dists) + dmax + entropy terms + euler --------
#define MBLK 256
__global__ void __launch_bounds__(MBLK)
k_mst(const float* __restrict__ pc, const float* __restrict__ rb,
      const float* __restrict__ rd, float* __restrict__ euler, int B) {
    __shared__ float spc[MBLK * NPTS * 3];
    {
        long long base = (long long)blockIdx.x * MBLK * (NPTS * 3);
        int nrow = B - blockIdx.x * MBLK;
        if (nrow >= MBLK) {
            const float4* src = (const float4*)(pc + base);
#pragma unroll 1
            for (int i = threadIdx.x; i < MBLK * NPTS * 3 / 4; i += MBLK)
                ((float4*)spc)[i] = src[i];
        } else if (nrow > 0) {
            int n = nrow * NPTS * 3;
            for (int i = threadIdx.x; i < n; i += MBLK) spc[i] = pc[base + i];
        }
    }
    __syncthreads();

    int b = blockIdx.x * blockDim.x + threadIdx.x;
    float s0 = 0.f, s1 = 0.f;
    if (b < B) {
        const float* p = spc + threadIdx.x * (NPTS * 3);
        float px[NPTS], py[NPTS], pz[NPTS];
#pragma unroll
        for (int i = 0; i < NPTS; i++) {
            px[i] = p[3 * i]; py[i] = p[3 * i + 1]; pz[i] = p[3 * i + 2];
        }
        float key[NPTS];
        float dmax2 = 0.f;
        key[0] = BIGF;
#pragma unroll
        for (int i = 1; i < NPTS; i++) {
            float dx = px[i] - px[0], dy = py[i] - py[0], dz = pz[i] - pz[0];
            float d2 = dx * dx + dy * dy + dz * dz;
            key[i] = d2;
            dmax2 = fmaxf(dmax2, d2);
        }
        float m1 = BIGF, m2 = BIGF;
#pragma unroll 1
        for (int it = 0; it < NEDGE; it++) {
#define MINP(AV, AI, BV, BI, OV, OI) \
            { bool c = (BV) < (AV); OV = c ? (BV) : (AV); OI = c ? (BI) : (AI); }
            float v12, v34, v56, v78, v910, v1112;
            int   i12, i34, i56, i78, i910, i1112;
            MINP(key[1], 1, key[2], 2, v12, i12)
            MINP(key[3], 3, key[4], 4, v34, i34)
            MINP(key[5], 5, key[6], 6, v56, i56)
            MINP(key[7], 7, key[8], 8, v78, i78)
            MINP(key[9], 9, key[10], 10, v910, i910)
            MINP(key[11], 11, key[12], 12, v1112, i1112)
            float va, vb, vc; int ia, ib, ic;
            MINP(v12, i12, v34, i34, va, ia)
            MINP(v56, i56, v78, i78, vb, ib)
            MINP(v910, i910, v1112, i1112, vc, ic)
            float vab; int iab;
            MINP(va, ia, vb, ib, vab, iab)
            float vcd; int icd;
            MINP(vc, ic, key[13], 13, vcd, icd)
            float bv; int bj;
            MINP(vab, iab, vcd, icd, bv, bj)
#undef MINP
            if (bv < m1) { m2 = m1; m1 = bv; } else if (bv < m2) { m2 = bv; }
            g_deaths0[it * B + b] = sqrtf(fmaxf(bv, 1e-24f));
            float qx = px[0], qy = py[0], qz = pz[0];
#pragma unroll
            for (int c = 1; c < NPTS; c++) {
                if (bj == c) { qx = px[c]; qy = py[c]; qz = pz[c]; }
            }
#pragma unroll
            for (int i = 1; i < NPTS; i++) {
                float dx = px[i] - qx, dy = py[i] - qy, dz = pz[i] - qz;
                float d2 = dx * dx + dy * dy + dz * dz;
                dmax2 = fmaxf(dmax2, d2);
                float nk = fminf(key[i], d2);
                key[i] = (i == bj || key[i] >= BIGF) ? BIGF : nk;
            }
        }
        float dmax = sqrtf(fmaxf(dmax2, 1e-24f));
        g_dmax[b] = dmax;
        float d0 = sqrtf(fmaxf(m1, 1e-24f));
        float d1 = sqrtf(fmaxf(m2, 1e-24f));
        float p0 = d1 - d0;
        g_p0[b] = p0;
        if (p0 > 0.f) s0 = p0;
        float p1b = (rb[b * NF1 + 1] - rb[b * NF1 + 0]) * dmax * 0.3f;
        float p1d = p1b + (rd[b * NF1 + 1] - rd[b * NF1 + 0]) * dmax * 0.4f;
        g_p1b[b] = p1b;
        g_p1d[b] = p1d;
        if (p1b > 0.f) s1 += p1b;
        if (p1d > 0.f) s1 += p1d;
        euler[b] = (float)(NEDGE - NF1);
    }
    __shared__ float s_e[2][8];
    int lane = threadIdx.x & 31, wid = threadIdx.x >> 5;
    int nw = blockDim.x >> 5;
    s0 = warp_red(s0);
    s1 = warp_red(s1);
    if (lane == 0) { s_e[0][wid] = s0; s_e[1][wid] = s1; }
    __syncthreads();
    if (wid == 0 && lane < 2) {
        float v = 0.f;
        for (int w = 0; w < nw; w++) v += s_e[lane][w];
        atomicAdd(&g_S[lane], v);
    }
}

// ---------------- diag0: piecewise tables, named float4 accumulators only ---------
__global__ void __launch_bounds__(256)
k_diag0(int total) {
    __shared__ float  sbp[H1];
    __shared__ __align__(16) float4 sA[NSEG * SROW4];
    __shared__ __align__(16) float4 sC[NSEG * SROW4];
    __shared__ float s_part[8][H2];
    for (int i = threadIdx.x; i < H1; i += blockDim.x) sbp[i] = g_bp[i];
    for (int i = threadIdx.x; i < NSEG * SROW4; i += blockDim.x) {
        sA[i] = g_A4[i];
        sC[i] = g_C4[i];
    }
    __syncthreads();
    float4 z = make_float4(0.f, 0.f, 0.f, 0.f);
    float4 a0 = z, a1 = z, a2 = z, a3 = z, a4 = z, a5 = z, a6 = z, a7 = z;
    int stride = gridDim.x * blockDim.x;
    for (int i = blockIdx.x * blockDim.x + threadIdx.x; i < total; i += stride) {
        float d = g_deaths0[i];
        int lo = 0, hi = H1;
#pragma unroll
        for (int s = 0; s < 6; s++) {
            int mid = (lo + hi) >> 1;
            if (sbp[mid] < d) lo = mid + 1; else hi = mid;
        }
        const float4* Av = sA + lo * SROW4;
        const float4* Cv = sC + lo * SROW4;
#define Q(ACC, q) { float4 A = Av[q], C = Cv[q];                          \
        ACC.x += fmaxf(fmaf(A.x, d, C.x), 0.f);                           \
        ACC.y += fmaxf(fmaf(A.y, d, C.y), 0.f);                           \
        ACC.z += fmaxf(fmaf(A.z, d, C.z), 0.f);                           \
        ACC.w += fmaxf(fmaf(A.w, d, C.w), 0.f); }
        Q(a0, 0) Q(a1, 1) Q(a2, 2) Q(a3, 3) Q(a4, 4) Q(a5, 5) Q(a6, 6) Q(a7, 7)
#undef Q
    }
    int lane = threadIdx.x & 31, wid = threadIdx.x >> 5;
    int nw = blockDim.x >> 5;
#define R(ACC, q) {                                                        \
    float vx = warp_red(ACC.x), vy = warp_red(ACC.y);                      \
    float vz = warp_red(ACC.z), vw = warp_red(ACC.w);                      \
    if (lane == 0) { s_part[wid][q * 4 + 0] = vx; s_part[wid][q * 4 + 1] = vy; \
                     s_part[wid][q * 4 + 2] = vz; s_part[wid][q * 4 + 3] = vw; } }
    R(a0, 0) R(a1, 1) R(a2, 2) R(a3, 3) R(a4, 4) R(a5, 5) R(a6, 6) R(a7, 7)
#undef R
    __syncthreads();
    if (threadIdx.x < H2) {
        float v = 0.f;
        for (int w = 0; w < nw; w++) v += s_part[w][threadIdx.x];
        atomicAdd(&g_h2sum[threadIdx.x], v);
    }
}

// ---------------- diag1: 2->64->32 MLP, k-pair packed f32x2, one kernel -----------
__global__ void __launch_bounds__(256)
k_diag1(const float* __restrict__ W1, const float* __restrict__ b1,
        const float* __restrict__ W2, const float* __restrict__ b2,
        const float* __restrict__ rb, const float* __restrict__ rd, int B) {
    __shared__ __align__(16) float sw[H1 * 4];        // (W1[0,j], W1[1,j], b1[j], 0)
    __shared__ __align__(16) u64 sW2p[H1 * 16];       // [j][kp]: packed (W2[j][2kp], W2[j][2kp+1])
    __shared__ __align__(16) u64 sb2p[16];            // packed bias pairs
    __shared__ float s_part[8][H2];
    for (int j = threadIdx.x; j < H1; j += blockDim.x) {
        sw[j * 4 + 0] = W1[j];
        sw[j * 4 + 1] = W1[H1 + j];
        sw[j * 4 + 2] = b1[j];
        sw[j * 4 + 3] = 0.f;
    }
    // identity copy: adjacent k-pairs of row-major W2 are already packed
    for (int i = threadIdx.x; i < H1 * 16; i += blockDim.x)
        sW2p[i] = ((const u64*)W2)[i];
    if (threadIdx.x < 16) sb2p[threadIdx.x] = ((const u64*)b2)[threadIdx.x];
    __syncthreads();

    float4 z = make_float4(0.f, 0.f, 0.f, 0.f);
    float4 a0 = z, a1 = z, a2 = z, a3 = z, a4 = z, a5 = z, a6 = z, a7 = z;

    int total = NF1 * B;
    int stride = gridDim.x * blockDim.x;
    for (int i = blockIdx.x * blockDim.x + threadIdx.x; i < total; i += stride) {
        float dm = g_dmax[i / NF1];
        float x = rb[i] * dm * 0.3f;
        float y = fmaf(rd[i] * dm, 0.4f, x);
        u64 tp0  = sb2p[0],  tp1  = sb2p[1],  tp2  = sb2p[2],  tp3  = sb2p[3];
        u64 tp4  = sb2p[4],  tp5  = sb2p[5],  tp6  = sb2p[6],  tp7  = sb2p[7];
        u64 tp8  = sb2p[8],  tp9  = sb2p[9],  tp10 = sb2p[10], tp11 = sb2p[11];
        u64 tp12 = sb2p[12], tp13 = sb2p[13], tp14 = sb2p[14], tp15 = sb2p[15];
#pragma unroll 1
        for (int jc = 0; jc < 4; jc++) {
            const float4* swv = (const float4*)sw + jc * 16;
            const ulonglong2* wrow = (const ulonglong2*)(sW2p + jc * 16 * 16);
#pragma unroll
            for (int jj = 0; jj < 16; jj++) {
                float4 w = swv[jj];
                float h = fmaxf(fmaf(x, w.x, fmaf(y, w.y, w.z)), 0.f);
                u64 hp = pack2(h, h);
                const ulonglong2* wp = wrow + jj * 8;
                ulonglong2 q0 = wp[0], q1 = wp[1], q2 = wp[2], q3 = wp[3];
                ulonglong2 q4 = wp[4], q5 = wp[5], q6 = wp[6], q7 = wp[7];
                FMA2(tp0,  hp, q0.x); FMA2(tp1,  hp, q0.y);
                FMA2(tp2,  hp, q1.x); FMA2(tp3,  hp, q1.y);
                FMA2(tp4,  hp, q2.x); FMA2(tp5,  hp, q2.y);
                FMA2(tp6,  hp, q3.x); FMA2(tp7,  hp, q3.y);
                FMA2(tp8,  hp, q4.x); FMA2(tp9,  hp, q4.y);
                FMA2(tp10, hp, q5.x); FMA2(tp11, hp, q5.y);
                FMA2(tp12, hp, q6.x); FMA2(tp13, hp, q6.y);
                FMA2(tp14, hp, q7.x); FMA2(tp15, hp, q7.y);
            }
        }
        // relu + accumulate (k = 2*kp, 2*kp+1)
        float lo, hi;
#define EP(TP, ACC, C0, C1) { unpack2(TP, lo, hi);                         \
        ACC.C0 += fmaxf(lo, 0.f); ACC.C1 += fmaxf(hi, 0.f); }
        EP(tp0,  a0, x, y) EP(tp1,  a0, z, w)
        EP(tp2,  a1, x, y) EP(tp3,  a1, z, w)
        EP(tp4,  a2, x, y) EP(tp5,  a2, z, w)
        EP(tp6,  a3, x, y) EP(tp7,  a3, z, w)
        EP(tp8,  a4, x, y) EP(tp9,  a4, z, w)
        EP(tp10, a5, x, y) EP(tp11, a5, z, w)
        EP(tp12, a6, x, y) EP(tp13, a6, z, w)
        EP(tp14, a7, x, y) EP(tp15, a7, z, w)
#undef EP
    }

    int lane = threadIdx.x & 31, wid = threadIdx.x >> 5;
    int nw = blockDim.x >> 5;
#define R(ACC, q) {                                                        \
    float vx = warp_red(ACC.x), vy = warp_red(ACC.y);                      \
    float vz = warp_red(ACC.z), vw = warp_red(ACC.w);                      \
    if (lane == 0) { s_part[wid][q * 4 + 0] = vx; s_part[wid][q * 4 + 1] = vy; \
                     s_part[wid][q * 4 + 2] = vz; s_part[wid][q * 4 + 3] = vw; } }
    R(a0, 0) R(a1, 1) R(a2, 2) R(a3, 3) R(a4, 4) R(a5, 5) R(a6, 6) R(a7, 7)
#undef R
    __syncthreads();
    if (threadIdx.x < H2) {
        float v = 0.f;
        for (int w = 0; w < nw; w++) v += s_part[w][threadIdx.x];
        atomicAdd(&g_h2sum[H2 + threadIdx.x], v);
    }
}

// ---------------- finale: features (block 0) + entropy (blocks 1..) --------------
__global__ void __launch_bounds__(512)
k_final(const float* __restrict__ W3, const float* __restrict__ b3,
        float* __restrict__ out, float* __restrict__ ent, int B) {
    if (blockIdx.x == 0) {
        __shared__ float u[H2];
        if (threadIdx.x < H2) {
            int k = threadIdx.x;
            u[k] = g_h2sum[k] / ((float)NEDGE * (float)B)
                 + g_h2sum[H2 + k] / ((float)NF1 * (float)B);
        }
        __syncthreads();
        int f = threadIdx.x;
        if (f < FDIM) {
            float t = 2.f * b3[f];
#pragma unroll
            for (int k = 0; k < H2; k++) t += u[k] * W3[k * FDIM + f];
            out[f] = t;
        }
        return;
    }
    int b = (blockIdx.x - 1) * blockDim.x + threadIdx.x;
    float t = 0.f;
    if (b < B) {
        float S0 = fmaxf(g_S[0], 1e-30f), S1 = fmaxf(g_S[1], 1e-30f);
        float p = g_p0[b];
        if (p > 0.f)  { float q = p  / S0; t -= q * logf(q + 1e-10f); }
        float pb = g_p1b[b];
        if (pb > 0.f) { float q = pb / S1; t -= q * logf(q + 1e-10f); }
        float pd = g_p1d[b];
        if (pd > 0.f) { float q = pd / S1; t -= q * logf(q + 1e-10f); }
    }
    __shared__ float sh[16];
    int lane = threadIdx.x & 31, wid = threadIdx.x >> 5;
    int nw = blockDim.x >> 5;
    t = warp_red(t);
    if (lane == 0) sh[wid] = t;
    __syncthreads();
    if (wid == 0) {
        t = (lane < nw) ? sh[lane] : 0.f;
#pragma unroll
        for (int o = 8; o; o >>= 1) t += __shfl_xor_sync(0xffffffffu, t, o);
        if (lane == 0) atomicAdd(ent, t);
    }
}

// ---------------- launch ----------------
extern "C" void kernel_launch(void* const* d_in, const int* in_sizes, int n_in,
                              void* d_out, int out_size) {
    const float* pc = (const float*)d_in[0];
    const float* rb = (const float*)d_in[1];
    const float* rd = (const float*)d_in[2];
    const float* W1 = (const float*)d_in[3];
    const float* b1 = (const float*)d_in[4];
    const float* W2 = (const float*)d_in[5];
    const float* b2 = (const float*)d_in[6];
    const float* W3 = (const float*)d_in[7];
    const float* b3 = (const float*)d_in[8];
    float* out = (float*)d_out;

    int B = in_sizes[1] / NF1;
    if (B > BMAX) B = BMAX;

    float* euler = out + FDIM;
    float* ent   = out + FDIM + B;

    k_setup<<<1, 256>>>(W1, b1, W2, b2, ent);
    k_mst<<<(B + MBLK - 1) / MBLK, MBLK>>>(pc, rb, rd, euler, B);
    k_diag1<<<(NF1 * B + 255) / 256, 256>>>(W1, b1, W2, b2, rb, rd, B);
    k_diag0<<<296, 256>>>(NEDGE * B);
    k_final<<<1 + (B + 511) / 512, 512>>>(W3, b3, out, ent, B);
}

// round 9
// speedup vs baseline: 1.0643x; 1.0643x over previous
#include <cuda_runtime.h>
#include <math.h>

#define NPTS  14
#define NEDGE 13
#define NF1   3
#define BMAX  65536
#define FDIM  512
#define H1    64
#define H2    32
#define NSEG  (H1 + 1)
#define SROW4 9            // 9 float4 = 36 floats padded row
#define BIGF  1e30f
#define VG    296          // virtual grid per role in fused diag kernel

// ---------------- scratch ----------------
__device__ float  g_deaths0[NEDGE * BMAX];
__device__ float  g_dmax[BMAX];
__device__ float  g_p0[BMAX];
__device__ float  g_p1b[BMAX];
__device__ float  g_p1d[BMAX];
__device__ float  g_S[2];
__device__ float  g_h2sum[2 * H2];
__device__ float  g_bp[H1];
__device__ float4 g_A4[NSEG * SROW4];
__device__ float4 g_C4[NSEG * SROW4];

__device__ __forceinline__ float warp_red(float v) {
#pragma unroll
    for (int o = 16; o; o >>= 1) v += __shfl_xor_sync(0xffffffffu, v, o);
    return v;
}

// dual 16-wide dot: loads weights once, feeds two independent FMA chains
__device__ __forceinline__ void dot16x2(
    float4 ha, float4 hb, float4 hc, float4 hd,
    float4 ea, float4 eb, float4 ec, float4 ed,
    const float* base, float& s0, float& s1) {
    const float4* wv = (const float4*)base;
    float4 w0 = wv[0], w1 = wv[1], w2 = wv[2], w3 = wv[3];
    s0 = fmaf(ha.x, w0.x, s0); s1 = fmaf(ea.x, w0.x, s1);
    s0 = fmaf(ha.y, w0.y, s0); s1 = fmaf(ea.y, w0.y, s1);
    s0 = fmaf(ha.z, w0.z, s0); s1 = fmaf(ea.z, w0.z, s1);
    s0 = fmaf(ha.w, w0.w, s0); s1 = fmaf(ea.w, w0.w, s1);
    s0 = fmaf(hb.x, w1.x, s0); s1 = fmaf(eb.x, w1.x, s1);
    s0 = fmaf(hb.y, w1.y, s0); s1 = fmaf(eb.y, w1.y, s1);
    s0 = fmaf(hb.z, w1.z, s0); s1 = fmaf(eb.z, w1.z, s1);
    s0 = fmaf(hb.w, w1.w, s0); s1 = fmaf(eb.w, w1.w, s1);
    s0 = fmaf(hc.x, w2.x, s0); s1 = fmaf(ec.x, w2.x, s1);
    s0 = fmaf(hc.y, w2.y, s0); s1 = fmaf(ec.y, w2.y, s1);
    s0 = fmaf(hc.z, w2.z, s0); s1 = fmaf(ec.z, w2.z, s1);
    s0 = fmaf(hc.w, w2.w, s0); s1 = fmaf(ec.w, w2.w, s1);
    s0 = fmaf(hd.x, w3.x, s0); s1 = fmaf(ed.x, w3.x, s1);
    s0 = fmaf(hd.y, w3.y, s0); s1 = fmaf(ed.y, w3.y, s1);
    s0 = fmaf(hd.z, w3.z, s0); s1 = fmaf(ed.z, w3.z, s1);
    s0 = fmaf(hd.w, w3.w, s0); s1 = fmaf(ed.w, w3.w, s1);
}

// ---------------- setup: zeros + breakpoints + segment tables ----------------
__global__ void k_setup(const float* __restrict__ W1, const float* __restrict__ b1,
                        const float* __restrict__ W2, const float* __restrict__ b2,
                        float* ent_slot) {
    __shared__ float sbp[H1];
    __shared__ float st[H1];
    int tid = threadIdx.x;
    if (tid < 2)  g_S[tid] = 0.f;
    if (tid < 64) g_h2sum[tid] = 0.f;
    if (tid == 0) *ent_slot = 0.f;
    if (tid < H1) {
        float w = W1[H1 + tid];
        st[tid] = (w != 0.f) ? (-b1[tid] / w) : __int_as_float(0x7f800000);
    }
    __syncthreads();
    if (tid < H1) {
        float t = st[tid];
        int r = 0;
#pragma unroll
        for (int i = 0; i < H1; i++) {
            float ti = st[i];
            r += (ti < t || (ti == t && i < tid)) ? 1 : 0;
        }
        sbp[r] = t;
        g_bp[r] = t;
    }
    __syncthreads();
    const float INF = __int_as_float(0x7f800000);
    for (int e = tid; e < NSEG * H2; e += blockDim.x) {
        int s = e >> 5, k = e & 31;
        float lo = (s == 0)  ? -INF : sbp[s - 1];
        float hi = (s == H1) ?  INF : sbp[s];
        float rep;
        bool li = isinf(lo), hiinf = isinf(hi);
        if (li && hiinf)      rep = 0.f;
        else if (li)          rep = hi - 1.f;
        else if (hiinf)       rep = lo + 1.f;
        else                  rep = 0.5f * (lo + hi);
        float A = 0.f, C = b2[k];
        for (int j = 0; j < H1; j++) {
            float w = W1[H1 + j], bb = b1[j];
            bool act = (w == 0.f) ? (bb > 0.f) : ((w * rep + bb) > 0.f);
            if (act) {
                float m = W2[j * H2 + k];
                A += w * m;
                C += bb * m;
            }
        }
        ((float*)g_A4)[s * (SROW4 * 4) + k] = A;
        ((float*)g_C4)[s * (SROW4 * 4) + k] = C;
    }
}

// ---------------- MST (Prim, squared dists) + dmax + entropy terms + euler --------
__global__ void __launch_bounds__(128)
k_mst(const float* __restrict__ pc, const float* __restrict__ rb,
      const float* __restrict__ rd, float* __restrict__ euler, int B) {
    __shared__ float spc[128 * NPTS * 3];
    {
        long long base = (long long)blockIdx.x * 128 * (NPTS * 3);
        int nrow = B - blockIdx.x * 128;
        if (nrow >= 128) {
            const float4* src = (const float4*)(pc + base);
#pragma unroll 1
            for (int i = threadIdx.x; i < 128 * NPTS * 3 / 4; i += 128)
                ((float4*)spc)[i] = src[i];
        } else if (nrow > 0) {
            int n = nrow * NPTS * 3;
            for (int i = threadIdx.x; i < n; i += 128) spc[i] = pc[base + i];
        }
    }
    __syncthreads();

    int b = blockIdx.x * blockDim.x + threadIdx.x;
    float s0 = 0.f, s1 = 0.f;
    if (b < B) {
        const float* p = spc + threadIdx.x * (NPTS * 3);
        float px[NPTS], py[NPTS], pz[NPTS];
#pragma unroll
        for (int i = 0; i < NPTS; i++) {
            px[i] = p[3 * i]; py[i] = p[3 * i + 1]; pz[i] = p[3 * i + 2];
        }
        float key[NPTS];
        float dmax2 = 0.f;
        key[0] = BIGF;
#pragma unroll
        for (int i = 1; i < NPTS; i++) {
            float dx = px[i] - px[0], dy = py[i] - py[0], dz = pz[i] - pz[0];
            float d2 = dx * dx + dy * dy + dz * dz;
            key[i] = d2;
            dmax2 = fmaxf(dmax2, d2);
        }
        float m1 = BIGF, m2 = BIGF;
#pragma unroll 1
        for (int it = 0; it < NEDGE; it++) {
#define MINP(AV, AI, BV, BI, OV, OI) \
            { bool c = (BV) < (AV); OV = c ? (BV) : (AV); OI = c ? (BI) : (AI); }
            float v12, v34, v56, v78, v910, v1112;
            int   i12, i34, i56, i78, i910, i1112;
            MINP(key[1], 1, key[2], 2, v12, i12)
            MINP(key[3], 3, key[4], 4, v34, i34)
            MINP(key[5], 5, key[6], 6, v56, i56)
            MINP(key[7], 7, key[8], 8, v78, i78)
            MINP(key[9], 9, key[10], 10, v910, i910)
            MINP(key[11], 11, key[12], 12, v1112, i1112)
            float va, vb, vc; int ia, ib, ic;
            MINP(v12, i12, v34, i34, va, ia)
            MINP(v56, i56, v78, i78, vb, ib)
            MINP(v910, i910, v1112, i1112, vc, ic)
            float vab; int iab;
            MINP(va, ia, vb, ib, vab, iab)
            float vcd; int icd;
            MINP(vc, ic, key[13], 13, vcd, icd)
            float bv; int bj;
            MINP(vab, iab, vcd, icd, bv, bj)
#undef MINP
            if (bv < m1) { m2 = m1; m1 = bv; } else if (bv < m2) { m2 = bv; }
            g_deaths0[it * B + b] = sqrtf(fmaxf(bv, 1e-24f));
            float qx = px[0], qy = py[0], qz = pz[0];
#pragma unroll
            for (int c = 1; c < NPTS; c++) {
                if (bj == c) { qx = px[c]; qy = py[c]; qz = pz[c]; }
            }
#pragma unroll
            for (int i = 1; i < NPTS; i++) {
                float dx = px[i] - qx, dy = py[i] - qy, dz = pz[i] - qz;
                float d2 = dx * dx + dy * dy + dz * dz;
                dmax2 = fmaxf(dmax2, d2);
                float nk = fminf(key[i], d2);
                key[i] = (i == bj || key[i] >= BIGF) ? BIGF : nk;
            }
        }
        float dmax = sqrtf(fmaxf(dmax2, 1e-24f));
        g_dmax[b] = dmax;
        float d0 = sqrtf(fmaxf(m1, 1e-24f));
        float d1 = sqrtf(fmaxf(m2, 1e-24f));
        float p0 = d1 - d0;
        g_p0[b] = p0;
        if (p0 > 0.f) s0 = p0;
        float p1b = (rb[b * NF1 + 1] - rb[b * NF1 + 0]) * dmax * 0.3f;
        float p1d = p1b + (rd[b * NF1 + 1] - rd[b * NF1 + 0]) * dmax * 0.4f;
        g_p1b[b] = p1b;
        g_p1d[b] = p1d;
        if (p1b > 0.f) s1 += p1b;
        if (p1d > 0.f) s1 += p1d;
        euler[b] = (float)(NEDGE - NF1);
    }
    __shared__ float s_e[2][4];
    int lane = threadIdx.x & 31, wid = threadIdx.x >> 5;
    int nw = blockDim.x >> 5;
    s0 = warp_red(s0);
    s1 = warp_red(s1);
    if (lane == 0) { s_e[0][wid] = s0; s_e[1][wid] = s1; }
    __syncthreads();
    if (wid == 0 && lane < 2) {
        float v = 0.f;
        for (int w = 0; w < nw; w++) v += s_e[lane][w];
        atomicAdd(&g_S[lane], v);
    }
}

// ---------------- fused diag kernel: role 0/1 = diag1 KC, role 2 = diag0 ----------
__global__ void __launch_bounds__(256)
k_diag(const float* __restrict__ W1, const float* __restrict__ b1,
       const float* __restrict__ W2, const float* __restrict__ b2,
       const float* __restrict__ rb, const float* __restrict__ rd, int B) {
    int role = blockIdx.x % 3;
    int vb   = blockIdx.x / 3;      // virtual block id 0..VG-1
    int lane = threadIdx.x & 31, wid = threadIdx.x >> 5;
    int nw = blockDim.x >> 5;

    if (role < 2) {
        // ======== diag1 path: 2->64->32 MLP, 16 k-outputs (KC = role) ========
        const int KC = role;
        __shared__ __align__(16) float sw[H1 * 4];       // (W1[0,j], W1[1,j], b1[j], 0)
        __shared__ __align__(16) float sW2t[16 * H1];    // this KC's 16 rows of W2^T
        __shared__ float sb2[16];
        __shared__ float s_part1[8][16];
        for (int j = threadIdx.x; j < H1; j += blockDim.x) {
            sw[j * 4 + 0] = W1[j];
            sw[j * 4 + 1] = W1[H1 + j];
            sw[j * 4 + 2] = b1[j];
            sw[j * 4 + 3] = 0.f;
        }
        for (int i = threadIdx.x; i < H1 * 16; i += blockDim.x) {
            int j = i >> 4, k = i & 15;
            sW2t[k * H1 + j] = W2[j * H2 + KC * 16 + k];
        }
        if (threadIdx.x < 16) sb2[threadIdx.x] = b2[KC * 16 + threadIdx.x];
        __syncthreads();

        float4 z = make_float4(0.f, 0.f, 0.f, 0.f);
        float4 ac0 = z, ac1 = z, ac2 = z, ac3 = z;

        int total = NF1 * B;
        int stride = VG * 256;
        for (int i = vb * 256 + threadIdx.x; i < total; i += 2 * stride) {
            int i2 = i + stride;
            bool has2 = (i2 < total);
            int i2v = has2 ? i2 : i;
            float dm0 = g_dmax[i / NF1];
            float dm1 = g_dmax[i2v / NF1];
            float x0 = rb[i] * dm0 * 0.3f;
            float y0 = fmaf(rd[i] * dm0, 0.4f, x0);
            float x1 = rb[i2v] * dm1 * 0.3f;
            float y1 = fmaf(rd[i2v] * dm1, 0.4f, x1);
            float4 ta0 = make_float4(sb2[0],  sb2[1],  sb2[2],  sb2[3]);
            float4 ta1 = make_float4(sb2[4],  sb2[5],  sb2[6],  sb2[7]);
            float4 ta2 = make_float4(sb2[8],  sb2[9],  sb2[10], sb2[11]);
            float4 ta3 = make_float4(sb2[12], sb2[13], sb2[14], sb2[15]);
            float4 tb0 = ta0, tb1 = ta1, tb2 = ta2, tb3 = ta3;
#pragma unroll 1
            for (int jc = 0; jc < 4; jc++) {
                const float4* swv = (const float4*)sw + jc * 16;
                float4 ha, hb, hc, hd;   // point 0
                float4 ea, eb, ec, ed;   // point 1
#define HV(D0, D1, COMP, IDX) { float4 w = swv[IDX];                            \
                D0.COMP = fmaxf(fmaf(x0, w.x, fmaf(y0, w.y, w.z)), 0.f);        \
                D1.COMP = fmaxf(fmaf(x1, w.x, fmaf(y1, w.y, w.z)), 0.f); }
                HV(ha, ea, x, 0)  HV(ha, ea, y, 1)  HV(ha, ea, z, 2)  HV(ha, ea, w, 3)
                HV(hb, eb, x, 4)  HV(hb, eb, y, 5)  HV(hb, eb, z, 6)  HV(hb, eb, w, 7)
                HV(hc, ec, x, 8)  HV(hc, ec, y, 9)  HV(hc, ec, z, 10) HV(hc, ec, w, 11)
                HV(hd, ed, x, 12) HV(hd, ed, y, 13) HV(hd, ed, z, 14) HV(hd, ed, w, 15)
#undef HV
                const float* wb = sW2t + jc * 16;
                dot16x2(ha, hb, hc, hd, ea, eb, ec, ed, wb + 0 * H1,  ta0.x, tb0.x);
                dot16x2(ha, hb, hc, hd, ea, eb, ec, ed, wb + 1 * H1,  ta0.y, tb0.y);
                dot16x2(ha, hb, hc, hd, ea, eb, ec, ed, wb + 2 * H1,  ta0.z, tb0.z);
                dot16x2(ha, hb, hc, hd, ea, eb, ec, ed, wb + 3 * H1,  ta0.w, tb0.w);
                dot16x2(ha, hb, hc, hd, ea, eb, ec, ed, wb + 4 * H1,  ta1.x, tb1.x);
                dot16x2(ha, hb, hc, hd, ea, eb, ec, ed, wb + 5 * H1,  ta1.y, tb1.y);
                dot16x2(ha, hb, hc, hd, ea, eb, ec, ed, wb + 6 * H1,  ta1.z, tb1.z);
                dot16x2(ha, hb, hc, hd, ea, eb, ec, ed, wb + 7 * H1,  ta1.w, tb1.w);
                dot16x2(ha, hb, hc, hd, ea, eb, ec, ed, wb + 8 * H1,  ta2.x, tb2.x);
                dot16x2(ha, hb, hc, hd, ea, eb, ec, ed, wb + 9 * H1,  ta2.y, tb2.y);
                dot16x2(ha, hb, hc, hd, ea, eb, ec, ed, wb + 10 * H1, ta2.z, tb2.z);
                dot16x2(ha, hb, hc, hd, ea, eb, ec, ed, wb + 11 * H1, ta2.w, tb2.w);
                dot16x2(ha, hb, hc, hd, ea, eb, ec, ed, wb + 12 * H1, ta3.x, tb3.x);
                dot16x2(ha, hb, hc, hd, ea, eb, ec, ed, wb + 13 * H1, ta3.y, tb3.y);
                dot16x2(ha, hb, hc, hd, ea, eb, ec, ed, wb + 14 * H1, ta3.z, tb3.z);
                dot16x2(ha, hb, hc, hd, ea, eb, ec, ed, wb + 15 * H1, ta3.w, tb3.w);
            }
            ac0.x += fmaxf(ta0.x, 0.f); ac0.y += fmaxf(ta0.y, 0.f);
            ac0.z += fmaxf(ta0.z, 0.f); ac0.w += fmaxf(ta0.w, 0.f);
            ac1.x += fmaxf(ta1.x, 0.f); ac1.y += fmaxf(ta1.y, 0.f);
            ac1.z += fmaxf(ta1.z, 0.f); ac1.w += fmaxf(ta1.w, 0.f);
            ac2.x += fmaxf(ta2.x, 0.f); ac2.y += fmaxf(ta2.y, 0.f);
            ac2.z += fmaxf(ta2.z, 0.f); ac2.w += fmaxf(ta2.w, 0.f);
            ac3.x += fmaxf(ta3.x, 0.f); ac3.y += fmaxf(ta3.y, 0.f);
            ac3.z += fmaxf(ta3.z, 0.f); ac3.w += fmaxf(ta3.w, 0.f);
            if (has2) {
                ac0.x += fmaxf(tb0.x, 0.f); ac0.y += fmaxf(tb0.y, 0.f);
                ac0.z += fmaxf(tb0.z, 0.f); ac0.w += fmaxf(tb0.w, 0.f);
                ac1.x += fmaxf(tb1.x, 0.f); ac1.y += fmaxf(tb1.y, 0.f);
                ac1.z += fmaxf(tb1.z, 0.f); ac1.w += fmaxf(tb1.w, 0.f);
                ac2.x += fmaxf(tb2.x, 0.f); ac2.y += fmaxf(tb2.y, 0.f);
                ac2.z += fmaxf(tb2.z, 0.f); ac2.w += fmaxf(tb2.w, 0.f);
                ac3.x += fmaxf(tb3.x, 0.f); ac3.y += fmaxf(tb3.y, 0.f);
                ac3.z += fmaxf(tb3.z, 0.f); ac3.w += fmaxf(tb3.w, 0.f);
            }
        }

#define R(ACC, q) {                                                        \
        float vx = warp_red(ACC.x), vy = warp_red(ACC.y);                  \
        float vz = warp_red(ACC.z), vw = warp_red(ACC.w);                  \
        if (lane == 0) { s_part1[wid][q * 4 + 0] = vx; s_part1[wid][q * 4 + 1] = vy; \
                         s_part1[wid][q * 4 + 2] = vz; s_part1[wid][q * 4 + 3] = vw; } }
        R(ac0, 0) R(ac1, 1) R(ac2, 2) R(ac3, 3)
#undef R
        __syncthreads();
        if (threadIdx.x < 16) {
            float v = 0.f;
            for (int w = 0; w < nw; w++) v += s_part1[w][threadIdx.x];
            atomicAdd(&g_h2sum[H2 + KC * 16 + threadIdx.x], v);
        }
    } else {
        // ======== diag0 path: piecewise tables over MST deaths ========
        __shared__ float  sbp[H1];
        __shared__ __align__(16) float4 sA[NSEG * SROW4];
        __shared__ __align__(16) float4 sC[NSEG * SROW4];
        __shared__ float s_part0[8][H2];
        for (int i = threadIdx.x; i < H1; i += blockDim.x) sbp[i] = g_bp[i];
        for (int i = threadIdx.x; i < NSEG * SROW4; i += blockDim.x) {
            sA[i] = g_A4[i];
            sC[i] = g_C4[i];
        }
        __syncthreads();
        float4 z = make_float4(0.f, 0.f, 0.f, 0.f);
        float4 a0 = z, a1 = z, a2 = z, a3 = z, a4 = z, a5 = z, a6 = z, a7 = z;
        int total = NEDGE * B;
        int stride = VG * 256;
        for (int i = vb * 256 + threadIdx.x; i < total; i += stride) {
            float d = g_deaths0[i];
            int lo = 0, hi = H1;
#pragma unroll
            for (int s = 0; s < 6; s++) {
                int mid = (lo + hi) >> 1;
                if (sbp[mid] < d) lo = mid + 1; else hi = mid;
            }
            const float4* Av = sA + lo * SROW4;
            const float4* Cv = sC + lo * SROW4;
#define Q(ACC, q) { float4 A = Av[q], C = Cv[q];                          \
            ACC.x += fmaxf(fmaf(A.x, d, C.x), 0.f);                       \
            ACC.y += fmaxf(fmaf(A.y, d, C.y), 0.f);                       \
            ACC.z += fmaxf(fmaf(A.z, d, C.z), 0.f);                       \
            ACC.w += fmaxf(fmaf(A.w, d, C.w), 0.f); }
            Q(a0, 0) Q(a1, 1) Q(a2, 2) Q(a3, 3) Q(a4, 4) Q(a5, 5) Q(a6, 6) Q(a7, 7)
#undef Q
        }
#define R(ACC, q) {                                                        \
        float vx = warp_red(ACC.x), vy = warp_red(ACC.y);                  \
        float vz = warp_red(ACC.z), vw = warp_red(ACC.w);                  \
        if (lane == 0) { s_part0[wid][q * 4 + 0] = vx; s_part0[wid][q * 4 + 1] = vy; \
                         s_part0[wid][q * 4 + 2] = vz; s_part0[wid][q * 4 + 3] = vw; } }
        R(a0, 0) R(a1, 1) R(a2, 2) R(a3, 3) R(a4, 4) R(a5, 5) R(a6, 6) R(a7, 7)
#undef R
        __syncthreads();
        if (threadIdx.x < H2) {
            float v = 0.f;
            for (int w = 0; w < nw; w++) v += s_part0[w][threadIdx.x];
            atomicAdd(&g_h2sum[threadIdx.x], v);
        }
    }
}

// ---------------- finale: features (block 0) + entropy (blocks 1..) --------------
__global__ void __launch_bounds__(512)
k_final(const float* __restrict__ W3, const float* __restrict__ b3,
        float* __restrict__ out, float* __restrict__ ent, int B) {
    if (blockIdx.x == 0) {
        __shared__ float u[H2];
        if (threadIdx.x < H2) {
            int k = threadIdx.x;
            u[k] = g_h2sum[k] / ((float)NEDGE * (float)B)
                 + g_h2sum[H2 + k] / ((float)NF1 * (float)B);
        }
        __syncthreads();
        int f = threadIdx.x;
        if (f < FDIM) {
            float t = 2.f * b3[f];
#pragma unroll
            for (int k = 0; k < H2; k++) t += u[k] * W3[k * FDIM + f];
            out[f] = t;
        }
        return;
    }
    int b = (blockIdx.x - 1) * blockDim.x + threadIdx.x;
    float t = 0.f;
    if (b < B) {
        float S0 = fmaxf(g_S[0], 1e-30f), S1 = fmaxf(g_S[1], 1e-30f);
        float p = g_p0[b];
        if (p > 0.f)  { float q = p  / S0; t -= q * logf(q + 1e-10f); }
        float pb = g_p1b[b];
        if (pb > 0.f) { float q = pb / S1; t -= q * logf(q + 1e-10f); }
        float pd = g_p1d[b];
        if (pd > 0.f) { float q = pd / S1; t -= q * logf(q + 1e-10f); }
    }
    __shared__ float sh[16];
    int lane = threadIdx.x & 31, wid = threadIdx.x >> 5;
    int nw = blockDim.x >> 5;
    t = warp_red(t);
    if (lane == 0) sh[wid] = t;
    __syncthreads();
    if (wid == 0) {
        t = (lane < nw) ? sh[lane] : 0.f;
#pragma unroll
        for (int o = 8; o; o >>= 1) t += __shfl_xor_sync(0xffffffffu, t, o);
        if (lane == 0) atomicAdd(ent, t);
    }
}

// ---------------- launch ----------------
extern "C" void kernel_launch(void* const* d_in, const int* in_sizes, int n_in,
                              void* d_out, int out_size) {
    const float* pc = (const float*)d_in[0];
    const float* rb = (const float*)d_in[1];
    const float* rd = (const float*)d_in[2];
    const float* W1 = (const float*)d_in[3];
    const float* b1 = (const float*)d_in[4];
    const float* W2 = (const float*)d_in[5];
    const float* b2 = (const float*)d_in[6];
    const float* W3 = (const float*)d_in[7];
    const float* b3 = (const float*)d_in[8];
    float* out = (float*)d_out;

    int B = in_sizes[1] / NF1;
    if (B > BMAX) B = BMAX;

    float* euler = out + FDIM;
    float* ent   = out + FDIM + B;

    k_setup<<<1, 256>>>(W1, b1, W2, b2, ent);
    k_mst<<<(B + 127) / 128, 128>>>(pc, rb, rd, euler, B);
    k_diag<<<3 * VG, 256>>>(W1, b1, W2, b2, rb, rd, B);
    k_final<<<1 + (B + 511) / 512, 512>>>(W3, b3, out, ent, B);
}

// round 11
// speedup vs baseline: 1.2860x; 1.2084x over previous
#include <cuda_runtime.h>
#include <math.h>

#define NPTS  14
#define NEDGE 13
#define NF1   3
#define BMAX  65536
#define FDIM  512
#define H1    64
#define H2    32
#define NSEG  (H1 + 1)
#define SROW4 9            // 9 float4 = 36 floats padded row
#define BIGF  1e30f

// ---------------- scratch ----------------
__device__ float  g_deaths0[NEDGE * BMAX];
__device__ float  g_dmax[BMAX];
__device__ float  g_p0[BMAX];
__device__ float  g_p1b[BMAX];
__device__ float  g_p1d[BMAX];
__device__ float  g_S[2];
__device__ float  g_h2sum[2 * H2];
__device__ float  g_bp0[H1];            // d-breakpoints (diag0 path, x=0)
__device__ float  g_bp1[H1];            // t-breakpoints (diag1 path, t=x/y)
__device__ float4 g_A4[NSEG * SROW4];   // diag0: slope rows
__device__ float4 g_C4[NSEG * SROW4];   // diag0: offset rows (b1,b2 baked)
__device__ float4 g_P4[NSEG * SROW4];   // diag1: t-slope rows
__device__ float4 g_Q4[NSEG * SROW4];   // diag1: t-offset rows (no bias)
__device__ int    g_fast;               // 1 iff b1 == 0 (homogeneous layer 1)

__device__ __forceinline__ float warp_red(float v) {
#pragma unroll
    for (int o = 16; o; o >>= 1) v += __shfl_xor_sync(0xffffffffu, v, o);
    return v;
}

// 16-wide dot (fallback path)
__device__ __forceinline__ float dot16(float4 ha, float4 hb, float4 hc, float4 hd,
                                       const float* base) {
    const float4* wv = (const float4*)base;
    float4 w0 = wv[0], w1 = wv[1], w2 = wv[2], w3 = wv[3];
    float s;
    s = ha.x * w0.x;
    s = fmaf(ha.y, w0.y, s); s = fmaf(ha.z, w0.z, s); s = fmaf(ha.w, w0.w, s);
    s = fmaf(hb.x, w1.x, s); s = fmaf(hb.y, w1.y, s); s = fmaf(hb.z, w1.z, s); s = fmaf(hb.w, w1.w, s);
    s = fmaf(hc.x, w2.x, s); s = fmaf(hc.y, w2.y, s); s = fmaf(hc.z, w2.z, s); s = fmaf(hc.w, w2.w, s);
    s = fmaf(hd.x, w3.x, s); s = fmaf(hd.y, w3.y, s); s = fmaf(hd.z, w3.z, s); s = fmaf(hd.w, w3.w, s);
    return s;
}

// ---------------- setup: zeros + breakpoints + tables + fast flag ----------------
__global__ void k_setup(const float* __restrict__ W1, const float* __restrict__ b1,
                        const float* __restrict__ W2, const float* __restrict__ b2,
                        float* ent_slot) {
    __shared__ float sb0[H1], sb1[H1], st[H1];
    __shared__ int s_nz;
    int tid = threadIdx.x;
    const float INF = __int_as_float(0x7f800000);
    if (tid == 0) s_nz = 0;
    if (tid < 2)  g_S[tid] = 0.f;
    if (tid < 64) g_h2sum[tid] = 0.f;
    if (tid == 0) *ent_slot = 0.f;
    __syncthreads();
    // pass 0: d-breakpoints  t_j = -b1_j / W1[1,j]
    if (tid < H1) {
        float w = W1[H1 + tid];
        st[tid] = (w != 0.f) ? (-b1[tid] / w) : INF;
        if (b1[tid] != 0.f) atomicAdd(&s_nz, 1);
    }
    __syncthreads();
    if (tid < H1) {
        float t = st[tid];
        int r = 0;
#pragma unroll
        for (int i = 0; i < H1; i++) {
            float ti = st[i];
            r += (ti < t || (ti == t && i < tid)) ? 1 : 0;
        }
        sb0[r] = t; g_bp0[r] = t;
    }
    __syncthreads();
    // pass 1: t-breakpoints  t_j = -W1[1,j] / W1[0,j]
    if (tid < H1) {
        float w0 = W1[tid], w1 = W1[H1 + tid];
        st[tid] = (w0 != 0.f) ? (-w1 / w0) : INF;
    }
    __syncthreads();
    if (tid < H1) {
        float t = st[tid];
        int r = 0;
#pragma unroll
        for (int i = 0; i < H1; i++) {
            float ti = st[i];
            r += (ti < t || (ti == t && i < tid)) ? 1 : 0;
        }
        sb1[r] = t; g_bp1[r] = t;
    }
    if (tid == 0) g_fast = (s_nz == 0) ? 1 : 0;
    __syncthreads();
    // build both table sets
    for (int e = tid; e < NSEG * H2; e += blockDim.x) {
        int s = e >> 5, k = e & 31;
        // ---- diag0 tables (segment in d) ----
        {
            float lo = (s == 0)  ? -INF : sb0[s - 1];
            float hi = (s == H1) ?  INF : sb0[s];
            float rep;
            bool li = isinf(lo), hiinf = isinf(hi);
            if (li && hiinf)      rep = 0.f;
            else if (li)          rep = hi - 1.f;
            else if (hiinf)       rep = lo + 1.f;
            else                  rep = 0.5f * (lo + hi);
            float A = 0.f, C = b2[k];
            for (int j = 0; j < H1; j++) {
                float w = W1[H1 + j], bb = b1[j];
                bool act = (w == 0.f) ? (bb > 0.f) : ((w * rep + bb) > 0.f);
                if (act) {
                    float m = W2[j * H2 + k];
                    A += w * m;
                    C += bb * m;
                }
            }
            ((float*)g_A4)[s * (SROW4 * 4) + k] = A;
            ((float*)g_C4)[s * (SROW4 * 4) + k] = C;
        }
        // ---- diag1 tables (segment in t = x/y, b1 = 0 assumed for use) ----
        {
            float lo = (s == 0)  ? -INF : sb1[s - 1];
            float hi = (s == H1) ?  INF : sb1[s];
            float rep;
            bool li = isinf(lo), hiinf = isinf(hi);
            if (li && hiinf)      rep = 0.f;
            else if (li)          rep = hi - 1.f;
            else if (hiinf)       rep = lo + 1.f;
            else                  rep = 0.5f * (lo + hi);
            float P = 0.f, Q = 0.f;
            for (int j = 0; j < H1; j++) {
                float w0 = W1[j], w1 = W1[H1 + j];
                bool act = (w0 == 0.f) ? (w1 > 0.f) : ((w0 * rep + w1) > 0.f);
                if (act) {
                    float m = W2[j * H2 + k];
                    P += w0 * m;
                    Q += w1 * m;
                }
            }
            ((float*)g_P4)[s * (SROW4 * 4) + k] = P;
            ((float*)g_Q4)[s * (SROW4 * 4) + k] = Q;
        }
    }
}

// ---------------- MST (Prim, squared dists) + dmax + entropy terms + euler --------
__global__ void __launch_bounds__(128)
k_mst(const float* __restrict__ pc, const float* __restrict__ rb,
      const float* __restrict__ rd, float* __restrict__ euler, int B) {
    __shared__ float spc[128 * NPTS * 3];
    {
        long long base = (long long)blockIdx.x * 128 * (NPTS * 3);
        int nrow = B - blockIdx.x * 128;
        if (nrow >= 128) {
            const float4* src = (const float4*)(pc + base);
#pragma unroll 1
            for (int i = threadIdx.x; i < 128 * NPTS * 3 / 4; i += 128)
                ((float4*)spc)[i] = src[i];
        } else if (nrow > 0) {
            int n = nrow * NPTS * 3;
            for (int i = threadIdx.x; i < n; i += 128) spc[i] = pc[base + i];
        }
    }
    __syncthreads();

    int b = blockIdx.x * blockDim.x + threadIdx.x;
    float s0 = 0.f, s1 = 0.f;
    if (b < B) {
        const float* p = spc + threadIdx.x * (NPTS * 3);
        float px[NPTS], py[NPTS], pz[NPTS];
#pragma unroll
        for (int i = 0; i < NPTS; i++) {
            px[i] = p[3 * i]; py[i] = p[3 * i + 1]; pz[i] = p[3 * i + 2];
        }
        float key[NPTS];
        float dmax2 = 0.f;
        key[0] = BIGF;
#pragma unroll
        for (int i = 1; i < NPTS; i++) {
            float dx = px[i] - px[0], dy = py[i] - py[0], dz = pz[i] - pz[0];
            float d2 = dx * dx + dy * dy + dz * dz;
            key[i] = d2;
            dmax2 = fmaxf(dmax2, d2);
        }
        float m1 = BIGF, m2 = BIGF;
#pragma unroll 1
        for (int it = 0; it < NEDGE; it++) {
#define MINP(AV, AI, BV, BI, OV, OI) \
            { bool c = (BV) < (AV); OV = c ? (BV) : (AV); OI = c ? (BI) : (AI); }
            float v12, v34, v56, v78, v910, v1112;
            int   i12, i34, i56, i78, i910, i1112;
            MINP(key[1], 1, key[2], 2, v12, i12)
            MINP(key[3], 3, key[4], 4, v34, i34)
            MINP(key[5], 5, key[6], 6, v56, i56)
            MINP(key[7], 7, key[8], 8, v78, i78)
            MINP(key[9], 9, key[10], 10, v910, i910)
            MINP(key[11], 11, key[12], 12, v1112, i1112)
            float va, vb, vc; int ia, ib, ic;
            MINP(v12, i12, v34, i34, va, ia)
            MINP(v56, i56, v78, i78, vb, ib)
            MINP(v910, i910, v1112, i1112, vc, ic)
            float vab; int iab;
            MINP(va, ia, vb, ib, vab, iab)
            float vcd; int icd;
            MINP(vc, ic, key[13], 13, vcd, icd)
            float bv; int bj;
            MINP(vab, iab, vcd, icd, bv, bj)
#undef MINP
            if (bv < m1) { m2 = m1; m1 = bv; } else if (bv < m2) { m2 = bv; }
            g_deaths0[it * B + b] = sqrtf(fmaxf(bv, 1e-24f));
            float qx = px[0], qy = py[0], qz = pz[0];
#pragma unroll
            for (int c = 1; c < NPTS; c++) {
                if (bj == c) { qx = px[c]; qy = py[c]; qz = pz[c]; }
            }
#pragma unroll
            for (int i = 1; i < NPTS; i++) {
                float dx = px[i] - qx, dy = py[i] - qy, dz = pz[i] - qz;
                float d2 = dx * dx + dy * dy + dz * dz;
                dmax2 = fmaxf(dmax2, d2);
                float nk = fminf(key[i], d2);
                key[i] = (i == bj || key[i] >= BIGF) ? BIGF : nk;
            }
        }
        float dmax = sqrtf(fmaxf(dmax2, 1e-24f));
        g_dmax[b] = dmax;
        float d0 = sqrtf(fmaxf(m1, 1e-24f));
        float d1 = sqrtf(fmaxf(m2, 1e-24f));
        float p0 = d1 - d0;
        g_p0[b] = p0;
        if (p0 > 0.f) s0 = p0;
        float p1b = (rb[b * NF1 + 1] - rb[b * NF1 + 0]) * dmax * 0.3f;
        float p1d = p1b + (rd[b * NF1 + 1] - rd[b * NF1 + 0]) * dmax * 0.4f;
        g_p1b[b] = p1b;
        g_p1d[b] = p1d;
        if (p1b > 0.f) s1 += p1b;
        if (p1d > 0.f) s1 += p1d;
        euler[b] = (float)(NEDGE - NF1);
    }
    __shared__ float s_e[2][4];
    int lane = threadIdx.x & 31, wid = threadIdx.x >> 5;
    int nw = blockDim.x >> 5;
    s0 = warp_red(s0);
    s1 = warp_red(s1);
    if (lane == 0) { s_e[0][wid] = s0; s_e[1][wid] = s1; }
    __syncthreads();
    if (wid == 0 && lane < 2) {
        float v = 0.f;
        for (int w = 0; w < nw; w++) v += s_e[lane][w];
        atomicAdd(&g_S[lane], v);
    }
}

// ---------------- fused diag: diag0 (hoisted row / search) + diag1 (t-table) ------
__global__ void __launch_bounds__(256)
k_diag(const float* __restrict__ W1, const float* __restrict__ b1,
       const float* __restrict__ W2, const float* __restrict__ b2,
       const float* __restrict__ rb, const float* __restrict__ rd, int B) {
    __shared__ float  sbp0[H1], sbp1[H1];
    __shared__ __align__(16) float4 sA[NSEG * SROW4];
    __shared__ __align__(16) float4 sC[NSEG * SROW4];
    __shared__ __align__(16) float4 sP[NSEG * SROW4];
    __shared__ __align__(16) float4 sQ[NSEG * SROW4];
    __shared__ __align__(16) float4 sb2v[8];
    __shared__ float s_part[8][H2];
    // fallback-only weights
    __shared__ __align__(16) float sw[H1 * 4];
    __shared__ __align__(16) float sW2t[H2 * H1];
    int tid = threadIdx.x;
    int fast = g_fast;
    for (int i = tid; i < H1; i += blockDim.x) { sbp0[i] = g_bp0[i]; sbp1[i] = g_bp1[i]; }
    for (int i = tid; i < NSEG * SROW4; i += blockDim.x) {
        sA[i] = g_A4[i]; sC[i] = g_C4[i];
        sP[i] = g_P4[i]; sQ[i] = g_Q4[i];
    }
    if (tid < 8) sb2v[tid] = ((const float4*)b2)[tid];
    if (!fast) {
        for (int j = tid; j < H1; j += blockDim.x) {
            sw[j * 4 + 0] = W1[j];
            sw[j * 4 + 1] = W1[H1 + j];
            sw[j * 4 + 2] = b1[j];
            sw[j * 4 + 3] = 0.f;
        }
        for (int i = tid; i < H1 * H2; i += blockDim.x) {
            int j = i / H2, k = i % H2;
            sW2t[k * H1 + j] = W2[i];
        }
    }
    __syncthreads();

    int lane = tid & 31, wid = tid >> 5;
    int nw = blockDim.x >> 5;
    int stride = gridDim.x * blockDim.x;
    int gbase = blockIdx.x * blockDim.x + tid;
    float4 z = make_float4(0.f, 0.f, 0.f, 0.f);

    // ================= phase A: diag0 over MST deaths =================
    {
        float4 a0 = z, a1 = z, a2 = z, a3 = z, a4 = z, a5 = z, a6 = z, a7 = z;
        int total = NEDGE * B;
        if (fast) {
            // b1 == 0 -> all d > 0 share one segment; hoist its row to registers
            int lo = 0, hi = H1;
#pragma unroll
            for (int s = 0; s < 6; s++) {
                int mid = (lo + hi) >> 1;
                if (sbp0[mid] < 1e-20f) lo = mid + 1; else hi = mid;
            }
            const float4* Av = sA + lo * SROW4;
            const float4* Cv = sC + lo * SROW4;
            float4 A0 = Av[0], A1 = Av[1], A2 = Av[2], A3 = Av[3];
            float4 A4 = Av[4], A5 = Av[5], A6 = Av[6], A7 = Av[7];
            float4 C0 = Cv[0], C1 = Cv[1], C2 = Cv[2], C3 = Cv[3];
            float4 C4 = Cv[4], C5 = Cv[5], C6 = Cv[6], C7 = Cv[7];
            for (int i = gbase; i < total; i += stride) {
                float d = g_deaths0[i];
#define Q0(ACC, AV, CV) {                                                 \
                ACC.x += fmaxf(fmaf(AV.x, d, CV.x), 0.f);                 \
                ACC.y += fmaxf(fmaf(AV.y, d, CV.y), 0.f);                 \
                ACC.z += fmaxf(fmaf(AV.z, d, CV.z), 0.f);                 \
                ACC.w += fmaxf(fmaf(AV.w, d, CV.w), 0.f); }
                Q0(a0, A0, C0) Q0(a1, A1, C1) Q0(a2, A2, C2) Q0(a3, A3, C3)
                Q0(a4, A4, C4) Q0(a5, A5, C5) Q0(a6, A6, C6) Q0(a7, A7, C7)
#undef Q0
            }
        } else {
            for (int i = gbase; i < total; i += stride) {
                float d = g_deaths0[i];
                int lo = 0, hi = H1;
#pragma unroll
                for (int s = 0; s < 6; s++) {
                    int mid = (lo + hi) >> 1;
                    if (sbp0[mid] < d) lo = mid + 1; else hi = mid;
                }
                const float4* Av = sA + lo * SROW4;
                const float4* Cv = sC + lo * SROW4;
#define Q1(ACC, q) { float4 A = Av[q], C = Cv[q];                         \
                ACC.x += fmaxf(fmaf(A.x, d, C.x), 0.f);                   \
                ACC.y += fmaxf(fmaf(A.y, d, C.y), 0.f);                   \
                ACC.z += fmaxf(fmaf(A.z, d, C.z), 0.f);                   \
                ACC.w += fmaxf(fmaf(A.w, d, C.w), 0.f); }
                Q1(a0, 0) Q1(a1, 1) Q1(a2, 2) Q1(a3, 3)
                Q1(a4, 4) Q1(a5, 5) Q1(a6, 6) Q1(a7, 7)
#undef Q1
            }
        }
#define R(ACC, q) {                                                        \
        float vx = warp_red(ACC.x), vy = warp_red(ACC.y);                  \
        float vz = warp_red(ACC.z), vw = warp_red(ACC.w);                  \
        if (lane == 0) { s_part[wid][q * 4 + 0] = vx; s_part[wid][q * 4 + 1] = vy; \
                         s_part[wid][q * 4 + 2] = vz; s_part[wid][q * 4 + 3] = vw; } }
        R(a0, 0) R(a1, 1) R(a2, 2) R(a3, 3) R(a4, 4) R(a5, 5) R(a6, 6) R(a7, 7)
        __syncthreads();
        if (tid < H2) {
            float v = 0.f;
            for (int w = 0; w < nw; w++) v += s_part[w][tid];
            atomicAdd(&g_h2sum[tid], v);
        }
        __syncthreads();
    }

    // ================= phase B: diag1 over random features =================
    {
        float4 c0 = z, c1 = z, c2 = z, c3 = z, c4 = z, c5 = z, c6 = z, c7 = z;
        int total = NF1 * B;
        if (fast) {
            float4 B0 = sb2v[0], B1 = sb2v[1], B2 = sb2v[2], B3 = sb2v[3];
            float4 B4 = sb2v[4], B5 = sb2v[5], B6 = sb2v[6], B7 = sb2v[7];
            for (int i = gbase; i < total; i += stride) {
                float dm = g_dmax[i / NF1];
                float x = rb[i] * dm * 0.3f;
                float y = fmaf(rd[i] * dm, 0.4f, x);
                float t = (y > 0.f) ? (x / y) : 0.f;
                int lo = 0, hi = H1;
#pragma unroll
                for (int s = 0; s < 6; s++) {
                    int mid = (lo + hi) >> 1;
                    if (sbp1[mid] < t) lo = mid + 1; else hi = mid;
                }
                const float4* Pv = sP + lo * SROW4;
                const float4* Qv = sQ + lo * SROW4;
#define Q2(ACC, q, BV) { float4 P = Pv[q], Q = Qv[q];                      \
                ACC.x += fmaxf(fmaf(y, fmaf(P.x, t, Q.x), BV.x), 0.f);     \
                ACC.y += fmaxf(fmaf(y, fmaf(P.y, t, Q.y), BV.y), 0.f);     \
                ACC.z += fmaxf(fmaf(y, fmaf(P.z, t, Q.z), BV.z), 0.f);     \
                ACC.w += fmaxf(fmaf(y, fmaf(P.w, t, Q.w), BV.w), 0.f); }
                Q2(c0, 0, B0) Q2(c1, 1, B1) Q2(c2, 2, B2) Q2(c3, 3, B3)
                Q2(c4, 4, B4) Q2(c5, 5, B5) Q2(c6, 6, B6) Q2(c7, 7, B7)
#undef Q2
            }
        } else {
            // exact per-point MLP (R6-proven form)
            for (int i = gbase; i < total; i += stride) {
                float dm = g_dmax[i / NF1];
                float x = rb[i] * dm * 0.3f;
                float y = fmaf(rd[i] * dm, 0.4f, x);
                float4 t0 = sb2v[0], t1 = sb2v[1], t2 = sb2v[2], t3 = sb2v[3];
                float4 t4 = sb2v[4], t5 = sb2v[5], t6 = sb2v[6], t7 = sb2v[7];
#pragma unroll 1
                for (int jc = 0; jc < 4; jc++) {
                    const float4* swv = (const float4*)sw + jc * 16;
                    float4 ha, hb, hc, hd;
#define HV(DST, COMP, IDX) { float4 w = swv[IDX];                              \
                    DST.COMP = fmaxf(fmaf(x, w.x, fmaf(y, w.y, w.z)), 0.f); }
                    HV(ha, x, 0)  HV(ha, y, 1)  HV(ha, z, 2)  HV(ha, w, 3)
                    HV(hb, x, 4)  HV(hb, y, 5)  HV(hb, z, 6)  HV(hb, w, 7)
                    HV(hc, x, 8)  HV(hc, y, 9)  HV(hc, z, 10) HV(hc, w, 11)
                    HV(hd, x, 12) HV(hd, y, 13) HV(hd, z, 14) HV(hd, w, 15)
#undef HV
                    const float* wb = sW2t + jc * 16;
                    t0.x += dot16(ha, hb, hc, hd, wb + 0 * H1);
                    t0.y += dot16(ha, hb, hc, hd, wb + 1 * H1);
                    t0.z += dot16(ha, hb, hc, hd, wb + 2 * H1);
                    t0.w += dot16(ha, hb, hc, hd, wb + 3 * H1);
                    t1.x += dot16(ha, hb, hc, hd, wb + 4 * H1);
                    t1.y += dot16(ha, hb, hc, hd, wb + 5 * H1);
                    t1.z += dot16(ha, hb, hc, hd, wb + 6 * H1);
                    t1.w += dot16(ha, hb, hc, hd, wb + 7 * H1);
                    t2.x += dot16(ha, hb, hc, hd, wb + 8 * H1);
                    t2.y += dot16(ha, hb, hc, hd, wb + 9 * H1);
                    t2.z += dot16(ha, hb, hc, hd, wb + 10 * H1);
                    t2.w += dot16(ha, hb, hc, hd, wb + 11 * H1);
                    t3.x += dot16(ha, hb, hc, hd, wb + 12 * H1);
                    t3.y += dot16(ha, hb, hc, hd, wb + 13 * H1);
                    t3.z += dot16(ha, hb, hc, hd, wb + 14 * H1);
                    t3.w += dot16(ha, hb, hc, hd, wb + 15 * H1);
                    t4.x += dot16(ha, hb, hc, hd, wb + 16 * H1);
                    t4.y += dot16(ha, hb, hc, hd, wb + 17 * H1);
                    t4.z += dot16(ha, hb, hc, hd, wb + 18 * H1);
                    t4.w += dot16(ha, hb, hc, hd, wb + 19 * H1);
                    t5.x += dot16(ha, hb, hc, hd, wb + 20 * H1);
                    t5.y += dot16(ha, hb, hc, hd, wb + 21 * H1);
                    t5.z += dot16(ha, hb, hc, hd, wb + 22 * H1);
                    t5.w += dot16(ha, hb, hc, hd, wb + 23 * H1);
                    t6.x += dot16(ha, hb, hc, hd, wb + 24 * H1);
                    t6.y += dot16(ha, hb, hc, hd, wb + 25 * H1);
                    t6.z += dot16(ha, hb, hc, hd, wb + 26 * H1);
                    t6.w += dot16(ha, hb, hc, hd, wb + 27 * H1);
                    t7.x += dot16(ha, hb, hc, hd, wb + 28 * H1);
                    t7.y += dot16(ha, hb, hc, hd, wb + 29 * H1);
                    t7.z += dot16(ha, hb, hc, hd, wb + 30 * H1);
                    t7.w += dot16(ha, hb, hc, hd, wb + 31 * H1);
                }
#define EP(TP, ACC) { ACC.x += fmaxf(TP.x, 0.f); ACC.y += fmaxf(TP.y, 0.f);    \
                      ACC.z += fmaxf(TP.z, 0.f); ACC.w += fmaxf(TP.w, 0.f); }
                EP(t0, c0) EP(t1, c1) EP(t2, c2) EP(t3, c3)
                EP(t4, c4) EP(t5, c5) EP(t6, c6) EP(t7, c7)
#undef EP
            }
        }
        R(c0, 0) R(c1, 1) R(c2, 2) R(c3, 3) R(c4, 4) R(c5, 5) R(c6, 6) R(c7, 7)
#undef R
        __syncthreads();
        if (tid < H2) {
            float v = 0.f;
            for (int w = 0; w < nw; w++) v += s_part[w][tid];
            atomicAdd(&g_h2sum[H2 + tid], v);
        }
    }
}

// ---------------- finale: features (block 0) + entropy (blocks 1..) --------------
__global__ void __launch_bounds__(512)
k_final(const float* __restrict__ W3, const float* __restrict__ b3,
        float* __restrict__ out, float* __restrict__ ent, int B) {
    if (blockIdx.x == 0) {
        __shared__ float u[H2];
        if (threadIdx.x < H2) {
            int k = threadIdx.x;
            u[k] = g_h2sum[k] / ((float)NEDGE * (float)B)
                 + g_h2sum[H2 + k] / ((float)NF1 * (float)B);
        }
        __syncthreads();
        int f = threadIdx.x;
        if (f < FDIM) {
            float t = 2.f * b3[f];
#pragma unroll
            for (int k = 0; k < H2; k++) t += u[k] * W3[k * FDIM + f];
            out[f] = t;
        }
        return;
    }
    int b = (blockIdx.x - 1) * blockDim.x + threadIdx.x;
    float t = 0.f;
    if (b < B) {
        float S0 = fmaxf(g_S[0], 1e-30f), S1 = fmaxf(g_S[1], 1e-30f);
        float p = g_p0[b];
        if (p > 0.f)  { float q = p  / S0; t -= q * logf(q + 1e-10f); }
        float pb = g_p1b[b];
        if (pb > 0.f) { float q = pb / S1; t -= q * logf(q + 1e-10f); }
        float pd = g_p1d[b];
        if (pd > 0.f) { float q = pd / S1; t -= q * logf(q + 1e-10f); }
    }
    __shared__ float sh[16];
    int lane = threadIdx.x & 31, wid = threadIdx.x >> 5;
    int nw = blockDim.x >> 5;
    t = warp_red(t);
    if (lane == 0) sh[wid] = t;
    __syncthreads();
    if (wid == 0) {
        t = (lane < nw) ? sh[lane] : 0.f;
#pragma unroll
        for (int o = 8; o; o >>= 1) t += __shfl_xor_sync(0xffffffffu, t, o);
        if (lane == 0) atomicAdd(ent, t);
    }
}

// ---------------- launch ----------------
extern "C" void kernel_launch(void* const* d_in, const int* in_sizes, int n_in,
                              void* d_out, int out_size) {
    const float* pc = (const float*)d_in[0];
    const float* rb = (const float*)d_in[1];
    const float* rd = (const float*)d_in[2];
    const float* W1 = (const float*)d_in[3];
    const float* b1 = (const float*)d_in[4];
    const float* W2 = (const float*)d_in[5];
    const float* b2 = (const float*)d_in[6];
    const float* W3 = (const float*)d_in[7];
    const float* b3 = (const float*)d_in[8];
    float* out = (float*)d_out;

    int B = in_sizes[1] / NF1;
    if (B > BMAX) B = BMAX;

    float* euler = out + FDIM;
    float* ent   = out + FDIM + B;

    k_setup<<<1, 256>>>(W1, b1, W2, b2, ent);
    k_mst<<<(B + 127) / 128, 128>>>(pc, rb, rd, euler, B);
    k_diag<<<296, 256>>>(W1, b1, W2, b2, rb, rd, B);
    k_final<<<1 + (B + 511) / 512, 512>>>(W3, b3, out, ent, B);
}